// round 2
// baseline (speedup 1.0000x reference)
#include <cuda_runtime.h>

// Problem constants (fixed by the dataset; guarded by runtime-derived sizes).
#define NMAX 100000
#define BV   32          // batch, and inner stride of xT / acc

// Scratch: x transposed to (N, B) and accumulator (M, B). 2 x 12.8 MB.
__device__ float g_xT [(size_t)NMAX * BV];
__device__ float g_acc[(size_t)NMAX * BV];

// ---------------------------------------------------------------------------
// Zero the accumulator (float4 stores, 800k threads).
__global__ void zero_acc_kernel(int total4) {
    int i = blockIdx.x * blockDim.x + threadIdx.x;
    if (i < total4) reinterpret_cast<float4*>(g_acc)[i] = make_float4(0.f, 0.f, 0.f, 0.f);
}

// ---------------------------------------------------------------------------
// Transpose x (B, N) -> g_xT (N, B). Tiled 32x32 through shared memory.
__global__ void transpose_x_kernel(const float* __restrict__ x, int N, int B) {
    __shared__ float tile[32][33];
    int n0 = blockIdx.x * 32;
    int tx = threadIdx.x, ty = threadIdx.y;
    int n = n0 + tx;
    if (ty < B && n < N)
        tile[ty][tx] = x[(size_t)ty * N + n];       // coalesced along n
    __syncthreads();
    int nw = n0 + ty;
    if (tx < B && nw < N)
        g_xT[(size_t)nw * BV + tx] = tile[tx][ty];  // coalesced along b
}

// ---------------------------------------------------------------------------
// Edge scatter: 8 threads per edge, one float4 (4 batches) per thread.
// Gather 128B row of xT[src], FMA by edge weight, vectorized red to acc[dst].
__global__ void edge_kernel(const int* __restrict__ idx,
                            const float* __restrict__ vals, int nnz) {
    int tid = blockIdx.x * blockDim.x + threadIdx.x;
    int e = tid >> 3;          // edge id
    int g = tid & 7;           // batch group (4 floats each)
    if (e >= nnz) return;

    int   src = __ldg(idx + e);
    int   dst = __ldg(idx + nnz + e);
    float v   = __ldg(vals + e);

    const float4* xp = reinterpret_cast<const float4*>(g_xT + (size_t)src * BV) + g;
    float4 xv = __ldg(xp);

    float* ap = g_acc + (size_t)dst * BV + g * 4;
    asm volatile("red.global.add.v4.f32 [%0], {%1, %2, %3, %4};"
                 :: "l"(ap), "f"(xv.x * v), "f"(xv.y * v),
                    "f"(xv.z * v), "f"(xv.w * v)
                 : "memory");
}

// ---------------------------------------------------------------------------
// Transpose acc (M, B) -> out (B, M) and add bias. Tiled 32x32.
__global__ void write_out_kernel(float* __restrict__ out,
                                 const float* __restrict__ bias, int M, int B) {
    __shared__ float tile[32][33];
    int m0 = blockIdx.x * 32;
    int tx = threadIdx.x, ty = threadIdx.y;
    int m = m0 + ty;
    if (m < M && tx < B)
        tile[ty][tx] = g_acc[(size_t)m * BV + tx];  // coalesced along b
    __syncthreads();
    int mo = m0 + tx;
    if (mo < M && ty < B)
        out[(size_t)ty * M + mo] = tile[tx][ty] + __ldg(bias + mo); // coalesced along m
}

// ---------------------------------------------------------------------------
extern "C" void kernel_launch(void* const* d_in, const int* in_sizes, int n_in,
                              void* d_out, int out_size) {
    const float* x    = (const float*)d_in[0];   // (B, N, 1)
    const int*   idx  = (const int*)  d_in[1];   // (2, NNZ): row0=src, row1=dst
    const float* vals = (const float*)d_in[2];   // (NNZ,)
    const float* bias = (const float*)d_in[3];   // (M, 1)
    float*       out  = (float*)d_out;           // (B, M, 1)

    int M   = in_sizes[3];
    int NNZ = in_sizes[1] / 2;
    int B   = out_size / M;
    int N   = in_sizes[0] / B;

    // 1) zero accumulator
    {
        int total4 = (M * B) / 4;
        zero_acc_kernel<<<(total4 + 255) / 256, 256>>>(total4);
    }
    // 2) transpose x -> xT (N, B)
    {
        dim3 blk(32, 32);
        transpose_x_kernel<<<(N + 31) / 32, blk>>>(x, N, B);
    }
    // 3) edge scatter with vectorized global reductions
    {
        long long threads = (long long)NNZ * 8;
        int blocks = (int)((threads + 255) / 256);
        edge_kernel<<<blocks, 256>>>(idx, vals, NNZ);
    }
    // 4) transpose acc -> out, add bias
    {
        dim3 blk(32, 32);
        write_out_kernel<<<(M + 31) / 32, blk>>>(out, bias, M, B);
    }
}